// round 6
// baseline (speedup 1.0000x reference)
#include <cuda_runtime.h>
#include <cuda_bf16.h>
#include <cstdint>

// ---------------- problem constants ----------------
#define B_   16
#define C_   64
#define H_   192
#define W_   192
#define NPIX (H_ * W_)

// ---------------- tiling ----------------
#define TR 8                  // tile rows
#define TC 32                 // tile cols (256 px, 64 oc per tile)
#define HR 10                 // halo rows
#define HC 34                 // halo cols
#define ROWB  144             // smem row pitch bytes (36 floats)
#define SLOTB 1456            // per-ci slot: 10*144=1440 + 16 pad (bank stagger)
#define BUFB  (C_ * SLOTB)    // 93184 B per buffer
#define SMEM_BYTES (2 * BUFB) // 186368 B -> 1 CTA/SM
#define TPC 4                 // tiles per CTA
#define THREADS 512

// Pre-packed W fragments: [b][tap][kf][hl][mf][lane] uint4 (mma A-frag order)
__device__ uint4 g_wfrag[B_ * 9 * 4 * 2 * 4 * 32];

// ---------------- helpers ----------------
__device__ __forceinline__ uint32_t smem_u32(const void* p) {
    uint32_t a;
    asm("{ .reg .u64 t; cvta.to.shared.u64 t, %1; cvt.u32.u64 %0, t; }" : "=r"(a) : "l"(p));
    return a;
}
__device__ __forceinline__ uint32_t cvt2(float lo, float hi) {
    uint32_t r;
    asm("cvt.rn.satfinite.bf16x2.f32 %0, %1, %2;" : "=r"(r) : "f"(hi), "f"(lo));
    return r;
}
__device__ __forceinline__ void split2(float v0, float v1, uint32_t& h2, uint32_t& l2) {
    h2 = cvt2(v0, v1);
    float h0 = __uint_as_float(h2 << 16);
    float h1 = __uint_as_float(h2 & 0xFFFF0000u);
    l2 = cvt2(v0 - h0, v1 - h1);
}
__device__ __forceinline__ void mma16816(float* c, const uint4& a, uint32_t b0, uint32_t b1) {
    asm volatile(
        "mma.sync.aligned.m16n8k16.row.col.f32.bf16.bf16.f32 "
        "{%0,%1,%2,%3}, {%4,%5,%6,%7}, {%8,%9}, {%0,%1,%2,%3};"
        : "+f"(c[0]), "+f"(c[1]), "+f"(c[2]), "+f"(c[3])
        : "r"(a.x), "r"(a.y), "r"(a.z), "r"(a.w), "r"(b0), "r"(b1));
}
__device__ __forceinline__ float lds_f32(uint32_t a) {
    float v;
    asm volatile("ld.shared.f32 %0, [%1];" : "=f"(v) : "r"(a));
    return v;
}

// ---------------- prep: interpolate + split + pack W fragments ----------------
__global__ void prep_w(const float* __restrict__ W0, const float* __restrict__ W1,
                       const float* __restrict__ DoT)
{
    const int tap = blockIdx.x;
    const int b   = blockIdx.y;
    const float d = DoT[b], od = 1.0f - d;

    const int t    = threadIdx.x;
    const int kf   = t >> 7;
    const int mf   = (t >> 5) & 3;
    const int lane = t & 31;
    const int m    = mf * 16 + (lane >> 2);
    const int k    = kf * 16 + (lane & 3) * 2;

    float v[4][2];
    #pragma unroll
    for (int r = 0; r < 4; r++) {
        const int oc = m + (r & 1) * 8;
        const int ci = k + (r >> 1) * 8;
        const size_t g0 = (size_t)(oc * C_ + ci) * 9 + tap;
        v[r][0] = od * W0[g0] + d * W1[g0];
        v[r][1] = od * W0[g0 + 9] + d * W1[g0 + 9];
    }
    uint4 hi, lo;
    uint32_t* hp = &hi.x;
    uint32_t* lp = &lo.x;
    #pragma unroll
    for (int r = 0; r < 4; r++) split2(v[r][0], v[r][1], hp[r], lp[r]);

    const size_t base = ((((size_t)(b * 9 + tap) * 4 + kf) * 2) * 4 + mf) * 32 + lane;
    g_wfrag[base]       = hi;
    g_wfrag[base + 128] = lo;
}

// ---------------- main kernel ----------------
__global__ __launch_bounds__(THREADS, 1)
void conv_mma(const float* __restrict__ x, float* __restrict__ y)
{
    extern __shared__ char smem[];
    const uint32_t sbase = smem_u32(smem);

    const int tid  = threadIdx.x;
    const int wid  = tid >> 5;
    const int lane = tid & 31;
    const int p_   = lane & 3;
    const int q    = lane >> 2;
    const int row  = wid & 7;       // tile row this warp computes
    const int mh   = wid >> 3;      // oc half: mf in {2mh, 2mh+1}
    const int b    = blockIdx.y;

    const float* xb = x + (size_t)b * C_ * NPIX;
    float* yb       = y + (size_t)b * C_ * NPIX;
    const uint4* wf = g_wfrag + (size_t)b * 9 * 1024;

    // ---- cp.async fill of one tile's raw fp32 halo into buffer `buf` ----
    auto issue_fill = [&](int t, int buf) {
        const int tile = blockIdx.x * TPC + t;
        const int hy0  = (tile / 6) * TR - 1;
        const int hx0  = (tile % 6) * TC - 1;
        const uint32_t sb = sbase + (uint32_t)buf * BUFB;
        for (int j = tid; j < C_ * HR * HC; j += THREADS) {
            const int ci  = j / (HR * HC);
            const int rem = j - ci * (HR * HC);
            const int r   = rem / HC;
            const int c   = rem - r * HC;
            const int gy  = hy0 + r;
            const int gx  = hx0 + c;
            const bool in = ((unsigned)gy < H_) && ((unsigned)gx < W_);
            const float* g = xb + (size_t)ci * NPIX + (in ? gy * W_ + gx : 0);
            const uint32_t sz = in ? 4u : 0u;   // zfill for padding
            const uint32_t sa = sb + (uint32_t)(ci * SLOTB + r * ROWB + c * 4);
            asm volatile("cp.async.ca.shared.global [%0], [%1], 4, %2;"
                         :: "r"(sa), "l"(g), "r"(sz) : "memory");
        }
        asm volatile("cp.async.commit_group;" ::: "memory");
    };

    issue_fill(0, 0);

    #pragma unroll
    for (int t = 0; t < TPC; t++) {
        if (t + 1 < TPC) {
            issue_fill(t + 1, (t + 1) & 1);
            asm volatile("cp.async.wait_group 1;" ::: "memory");
        } else {
            asm volatile("cp.async.wait_group 0;" ::: "memory");
        }
        __syncthreads();

        const int tile = blockIdx.x * TPC + t;
        const int py0  = (tile / 6) * TR;
        const int px0  = (tile % 6) * TC;
        const uint32_t sbuf = sbase + (uint32_t)(t & 1) * BUFB;
        const uint32_t thr_off = (uint32_t)(2 * p_ * SLOTB + q * 4);

        float acc[2][4][4];
        #pragma unroll
        for (int i = 0; i < 2; i++)
            #pragma unroll
            for (int cs = 0; cs < 4; cs++) {
                acc[i][cs][0] = 0.f; acc[i][cs][1] = 0.f;
                acc[i][cs][2] = 0.f; acc[i][cs][3] = 0.f;
            }

        for (int tap = 0; tap < 9; tap++) {
            const int ky = tap / 3;
            const int kx = tap - ky * 3;
            const uint4* wft = wf + tap * 1024;
            const uint32_t tap_off = (uint32_t)((row + ky) * ROWB + kx * 4);

            #pragma unroll
            for (int kf = 0; kf < 4; kf++) {
                const uint4* wfk = wft + kf * 256;
                const uint4 ah0 = wfk[(2 * mh)     * 32 + lane];
                const uint4 ah1 = wfk[(2 * mh + 1) * 32 + lane];
                const uint4 al0 = wfk[128 + (2 * mh)     * 32 + lane];
                const uint4 al1 = wfk[128 + (2 * mh + 1) * 32 + lane];
                const uint32_t a0 = sbuf + (uint32_t)(kf * 16 * SLOTB) + thr_off + tap_off;

                #pragma unroll
                for (int cs = 0; cs < 4; cs++) {
                    const uint32_t ad = a0 + cs * 32;   // cs*8 px * 4B
                    const float v00 = lds_f32(ad);
                    const float v01 = lds_f32(ad + SLOTB);
                    const float v10 = lds_f32(ad + 8 * SLOTB);
                    const float v11 = lds_f32(ad + 9 * SLOTB);
                    uint32_t bh0, bl0, bh1, bl1;
                    split2(v00, v01, bh0, bl0);
                    split2(v10, v11, bh1, bl1);
                    mma16816(acc[0][cs], ah0, bh0, bh1);
                    mma16816(acc[1][cs], ah1, bh0, bh1);
                    mma16816(acc[0][cs], al0, bh0, bh1);
                    mma16816(acc[1][cs], al1, bh0, bh1);
                    mma16816(acc[0][cs], ah0, bl0, bl1);
                    mma16816(acc[1][cs], ah1, bl0, bl1);
                }
            }
        }

        // ---- epilogue ----
        const int gy = py0 + row;
        #pragma unroll
        for (int i = 0; i < 2; i++) {
            const int oc = (2 * mh + i) * 16 + q;
            #pragma unroll
            for (int cs = 0; cs < 4; cs++) {
                const int gx = px0 + cs * 8 + 2 * p_;
                float2* o0 = (float2*)(yb + (size_t)oc * NPIX + gy * W_ + gx);
                *o0 = make_float2(acc[i][cs][0], acc[i][cs][1]);
                float2* o1 = (float2*)(yb + (size_t)(oc + 8) * NPIX + gy * W_ + gx);
                *o1 = make_float2(acc[i][cs][2], acc[i][cs][3]);
            }
        }
        __syncthreads();   // all reads of buf[t&1] done before next fill reuses it
    }
}

// ---------------- launch ----------------
extern "C" void kernel_launch(void* const* d_in, const int* in_sizes, int n_in,
                              void* d_out, int out_size)
{
    const float* x   = (const float*)d_in[0];
    const float* DoT = (const float*)d_in[1];
    const float* W0  = (const float*)d_in[2];
    const float* W1  = (const float*)d_in[3];
    float* y = (float*)d_out;

    cudaFuncSetAttribute(conv_mma, cudaFuncAttributeMaxDynamicSharedMemorySize, SMEM_BYTES);

    prep_w<<<dim3(9, B_), 512>>>(W0, W1, DoT);
    // tiles: 24 rows x 6 cols = 144 per batch; 4 per CTA -> grid.x = 36
    conv_mma<<<dim3(36, B_), THREADS, SMEM_BYTES>>>(x, y);
}

// round 7
// speedup vs baseline: 1.0148x; 1.0148x over previous
#include <cuda_runtime.h>
#include <cuda_bf16.h>
#include <cstdint>

// ---------------- problem constants ----------------
#define B_   16
#define C_   64
#define H_   192
#define W_   192
#define NPIX (H_ * W_)

// ---------------- tiling ----------------
#define TR 4                  // tile rows
#define TC 32                 // tile cols (128 px, 64 oc per tile)
#define HR 6                  // halo rows
#define HC 34                 // halo cols
#define TPC 8                 // tiles per CTA (consecutive)

// split smem (bf16 hi/lo, R5 layout): [slot=kf*4+p (16)][row 6][col 34][e 2 words]
#define ROWB   272            // 34 * 8 B
#define SLOTB  1648           // 6*272 = 1632 + 16 pad
#define IMGB   (16 * SLOTB)   // 26368 B per image
#define SPLITB (2 * IMGB)     // 52736 B (hi, then lo)

// fp32 staging: [ci 64][row 6][col 34] raw
#define SROWB  136            // 34 * 4 B
#define SSLOTB 832            // 6*136 = 816 + 16 pad
#define STGB   (C_ * SSLOTB)  // 53248 B

#define SMEM_BYTES (SPLITB + STGB)   // 105984 -> 2 CTAs/SM

// Pre-packed W fragments: [b][tap][kf][hl][mf][lane] uint4 (mma A-frag order)
__device__ uint4 g_wfrag[B_ * 9 * 4 * 2 * 4 * 32];

// ---------------- helpers ----------------
__device__ __forceinline__ uint32_t smem_u32(const void* p) {
    uint32_t a;
    asm("{ .reg .u64 t; cvta.to.shared.u64 t, %1; cvt.u32.u64 %0, t; }" : "=r"(a) : "l"(p));
    return a;
}
__device__ __forceinline__ uint32_t cvt2(float lo, float hi) {
    uint32_t r;
    asm("cvt.rn.satfinite.bf16x2.f32 %0, %1, %2;" : "=r"(r) : "f"(hi), "f"(lo));
    return r;
}
__device__ __forceinline__ void split2(float v0, float v1, uint32_t& h2, uint32_t& l2) {
    h2 = cvt2(v0, v1);
    float h0 = __uint_as_float(h2 << 16);
    float h1 = __uint_as_float(h2 & 0xFFFF0000u);
    l2 = cvt2(v0 - h0, v1 - h1);
}
__device__ __forceinline__ void mma16816(float* c, const uint4& a, uint32_t b0, uint32_t b1) {
    asm volatile(
        "mma.sync.aligned.m16n8k16.row.col.f32.bf16.bf16.f32 "
        "{%0,%1,%2,%3}, {%4,%5,%6,%7}, {%8,%9}, {%0,%1,%2,%3};"
        : "+f"(c[0]), "+f"(c[1]), "+f"(c[2]), "+f"(c[3])
        : "r"(a.x), "r"(a.y), "r"(a.z), "r"(a.w), "r"(b0), "r"(b1));
}

// ---------------- prep: interpolate + split + pack W fragments ----------------
__global__ void prep_w(const float* __restrict__ W0, const float* __restrict__ W1,
                       const float* __restrict__ DoT)
{
    const int tap = blockIdx.x;
    const int b   = blockIdx.y;
    const float d = DoT[b], od = 1.0f - d;

    const int t    = threadIdx.x;
    const int kf   = t >> 7;
    const int mf   = (t >> 5) & 3;
    const int lane = t & 31;
    const int m    = mf * 16 + (lane >> 2);
    const int k    = kf * 16 + (lane & 3) * 2;

    float v[4][2];
    #pragma unroll
    for (int r = 0; r < 4; r++) {
        const int oc = m + (r & 1) * 8;
        const int ci = k + (r >> 1) * 8;
        const size_t g0 = (size_t)(oc * C_ + ci) * 9 + tap;
        v[r][0] = od * W0[g0] + d * W1[g0];
        v[r][1] = od * W0[g0 + 9] + d * W1[g0 + 9];
    }
    uint4 hi, lo;
    uint32_t* hp = &hi.x;
    uint32_t* lp = &lo.x;
    #pragma unroll
    for (int r = 0; r < 4; r++) split2(v[r][0], v[r][1], hp[r], lp[r]);

    const size_t base = ((((size_t)(b * 9 + tap) * 4 + kf) * 2) * 4 + mf) * 32 + lane;
    g_wfrag[base]       = hi;
    g_wfrag[base + 128] = lo;
}

// ---------------- main kernel ----------------
__global__ __launch_bounds__(256, 2)
void conv_mma(const float* __restrict__ x, float* __restrict__ y)
{
    extern __shared__ char smem[];
    const uint32_t sx  = smem_u32(smem);          // split buffer base
    const uint32_t stg = sx + SPLITB;             // staging base

    const int tid  = threadIdx.x;
    const int wid  = tid >> 5;
    const int lane = tid & 31;
    const int p_   = lane & 3;
    const int q    = lane >> 2;
    const int row  = wid & 3;        // tile row this warp computes
    const int mh   = wid >> 2;       // oc half: mf in {2mh, 2mh+1}
    const int b    = blockIdx.y;

    const float* xb = x + (size_t)b * C_ * NPIX;
    float* yb       = y + (size_t)b * C_ * NPIX;
    const uint4* wf = g_wfrag + (size_t)b * 9 * 1024;

    // ---- cp.async fill of one tile's raw fp32 halo into staging ----
    auto issue_fill = [&](int t) {
        const int tile = blockIdx.x * TPC + t;
        const int hy0  = (tile / 6) * TR - 1;
        const int hx0  = (tile % 6) * TC - 1;
        for (int j = tid; j < C_ * HR * HC; j += 256) {
            const int ci  = j / (HR * HC);
            const int rem = j - ci * (HR * HC);
            const int r   = rem / HC;
            const int c   = rem - r * HC;
            const int gy  = hy0 + r;
            const int gx  = hx0 + c;
            const bool in = ((unsigned)gy < H_) && ((unsigned)gx < W_);
            const float* g = xb + (size_t)ci * NPIX + (in ? gy * W_ + gx : 0);
            const uint32_t sz = in ? 4u : 0u;     // zfill padding
            const uint32_t sa = stg + (uint32_t)(ci * SSLOTB + r * SROWB + c * 4);
            asm volatile("cp.async.ca.shared.global [%0], [%1], 4, %2;"
                         :: "r"(sa), "l"(g), "r"(sz) : "memory");
        }
        asm volatile("cp.async.commit_group;" ::: "memory");
    };

    // ---- convert: staging fp32 -> split bf16 hi/lo (R5 layout) ----
    auto convert = [&]() {
        for (int j = tid; j < 16 * HR * HC; j += 256) {
            const int slot = j / (HR * HC);
            const int rem  = j - slot * (HR * HC);
            const int r    = rem / HC;
            const int c    = rem - r * HC;
            const int kfi  = slot >> 2;
            const int pp   = slot & 3;
            const uint32_t dbase = sx + (uint32_t)(slot * SLOTB + r * ROWB + c * 8);
            #pragma unroll
            for (int e = 0; e < 2; e++) {
                const int ch = 2 * (kfi * 8 + pp + 4 * e);
                const uint32_t a0 = stg + (uint32_t)(ch * SSLOTB + r * SROWB + c * 4);
                float v0, v1;
                asm volatile("ld.shared.f32 %0, [%1];" : "=f"(v0) : "r"(a0));
                asm volatile("ld.shared.f32 %0, [%1];" : "=f"(v1) : "r"(a0 + SSLOTB));
                uint32_t h2, l2;
                split2(v0, v1, h2, l2);
                asm volatile("st.shared.b32 [%0], %1;" :: "r"(dbase + e * 4), "r"(h2) : "memory");
                asm volatile("st.shared.b32 [%0], %1;" :: "r"(dbase + IMGB + e * 4), "r"(l2) : "memory");
            }
        }
    };

    // ---- prologue: fill+convert tile 0, start fill of tile 1 ----
    issue_fill(0);
    asm volatile("cp.async.wait_group 0;" ::: "memory");
    __syncthreads();
    convert();
    __syncthreads();
    issue_fill(1);

    const uint32_t thr_off = (uint32_t)(p_ * SLOTB + q * 8);

    for (int t = 0; t < TPC; t++) {
        const int tile = blockIdx.x * TPC + t;
        const int py0  = (tile / 6) * TR;
        const int px0  = (tile % 6) * TC;

        float acc[2][4][4];
        #pragma unroll
        for (int i = 0; i < 2; i++)
            #pragma unroll
            for (int cs = 0; cs < 4; cs++) {
                acc[i][cs][0] = 0.f; acc[i][cs][1] = 0.f;
                acc[i][cs][2] = 0.f; acc[i][cs][3] = 0.f;
            }

        for (int tap = 0; tap < 9; tap++) {
            const int ky = tap / 3;
            const int kx = tap - ky * 3;
            const uint4* wft = wf + tap * 1024;
            const uint32_t tap_off = (uint32_t)((row + ky) * ROWB + kx * 8);

            #pragma unroll
            for (int kf = 0; kf < 4; kf++) {
                const uint4* wfk = wft + kf * 256;
                const uint4 ah0 = wfk[(2 * mh)     * 32 + lane];
                const uint4 ah1 = wfk[(2 * mh + 1) * 32 + lane];
                const uint4 al0 = wfk[128 + (2 * mh)     * 32 + lane];
                const uint4 al1 = wfk[128 + (2 * mh + 1) * 32 + lane];
                const uint32_t a_base = sx + (uint32_t)(kf * 4 * SLOTB) + thr_off + tap_off;

                #pragma unroll
                for (int cs = 0; cs < 4; cs++) {
                    const uint32_t ad = a_base + cs * 64;
                    uint32_t bh0, bh1, bl0, bl1;
                    asm volatile("ld.shared.v2.b32 {%0,%1}, [%2];"
                                 : "=r"(bh0), "=r"(bh1) : "r"(ad));
                    asm volatile("ld.shared.v2.b32 {%0,%1}, [%2];"
                                 : "=r"(bl0), "=r"(bl1) : "r"(ad + IMGB));
                    mma16816(acc[0][cs], ah0, bh0, bh1);
                    mma16816(acc[1][cs], ah1, bh0, bh1);
                    mma16816(acc[0][cs], al0, bh0, bh1);
                    mma16816(acc[1][cs], al1, bh0, bh1);
                    mma16816(acc[0][cs], ah0, bl0, bl1);
                    mma16816(acc[1][cs], ah1, bl0, bl1);
                }
            }
        }

        // ---- epilogue ----
        const int gy = py0 + row;
        #pragma unroll
        for (int i = 0; i < 2; i++) {
            const int oc = (2 * mh + i) * 16 + q;
            #pragma unroll
            for (int cs = 0; cs < 4; cs++) {
                const int gx = px0 + cs * 8 + 2 * p_;
                float2* o0 = (float2*)(yb + (size_t)oc * NPIX + gy * W_ + gx);
                *o0 = make_float2(acc[i][cs][0], acc[i][cs][1]);
                float2* o1 = (float2*)(yb + (size_t)(oc + 8) * NPIX + gy * W_ + gx);
                *o1 = make_float2(acc[i][cs][2], acc[i][cs][3]);
            }
        }

        // ---- rotate pipeline: convert t+1, start fill t+2 ----
        if (t + 1 < TPC) {
            asm volatile("cp.async.wait_group 0;" ::: "memory");
            __syncthreads();           // compute reads of split buf done; staging ready
            convert();
            __syncthreads();           // staging fully consumed; split buf ready
            if (t + 2 < TPC) issue_fill(t + 2);
        }
    }
}

// ---------------- launch ----------------
extern "C" void kernel_launch(void* const* d_in, const int* in_sizes, int n_in,
                              void* d_out, int out_size)
{
    const float* x   = (const float*)d_in[0];
    const float* DoT = (const float*)d_in[1];
    const float* W0  = (const float*)d_in[2];
    const float* W1  = (const float*)d_in[3];
    float* y = (float*)d_out;

    cudaFuncSetAttribute(conv_mma, cudaFuncAttributeMaxDynamicSharedMemorySize, SMEM_BYTES);

    prep_w<<<dim3(9, B_), 512>>>(W0, W1, DoT);
    // tiles: 48 row-tiles x 6 col-tiles = 288 per batch; 8 per CTA -> grid.x = 36
    conv_mma<<<dim3(36, B_), 256, SMEM_BYTES>>>(x, y);
}